// round 16
// baseline (speedup 1.0000x reference)
#include <cuda_runtime.h>
#include <cstddef>

// Problem constants (fixed by setup_inputs)
constexpr int B = 8;
constexpr int C = 144;
constexpr int N = 4096;
constexpr int K = 16;
constexpr int G = 9;
constexpr int D = 16;          // C / G
constexpr int NTILE = 64;      // points per transpose block
constexpr int NBLK_N = N / NTILE;

constexpr int FEAT_ELEMS = B * C * N;      // 4718592
constexpr int CENT_ELEMS = B * G * N;      // 294912
constexpr int IDX_ELEMS  = B * N * K;      // 524288
constexpr int TBLOCKS    = B * G * NBLK_N; // 4608 (= CENT_ELEMS / 64)

constexpr int PTS      = 32;               // points per attn inner iteration
constexpr int CHUNKS   = 8;                // blocks per bg slab
constexpr int CHUNK_PTS = N / CHUNKS;      // 512 points per block
constexpr int ITERS    = CHUNK_PTS / PTS;  // 16 inner iterations
constexpr int ABLOCKS  = B * G * CHUNKS;   // 576

// Fused scratch: per point one 128B row = [key(16 floats) | value(16 floats)].
__device__ __align__(128) float g_qkv[(size_t)B * G * N * 32];

// Index-dtype flag: 1 if idx_knn is int64, 0 if int32.
__device__ int g_idx_is64;

// ---------------------------------------------------------------------------
// Transpose (B, C, N) -> fused (B*G, N, 32) rows, zero the centrality region,
// and (block 0 only) detect the idx dtype.
// ---------------------------------------------------------------------------
__global__ void __launch_bounds__(256) transpose_kernel(
    const float* __restrict__ qk, const float* __restrict__ val,
    const unsigned int* __restrict__ idx_raw,
    float* __restrict__ cent)
{
    __shared__ float tile[D][NTILE + 1];
    __shared__ unsigned int s_any;

    const int blk   = blockIdx.x;
    const int ntile = blk % NBLK_N;
    const int bg    = blk / NBLK_N;
    const int g     = bg % G;
    const int b     = bg / G;
    const int n0    = ntile * NTILE;
    const int tid   = threadIdx.x;

    // ---- block 0: idx dtype detection (odd words all zero => int64) ----
    if (blk == 0) {
        if (tid == 0) s_any = 0u;
        __syncthreads();
        unsigned int v = idx_raw[2 * tid + 1] |
                         idx_raw[2 * (tid + 256) + 1] |
                         idx_raw[2 * (tid + 512) + 1] |
                         idx_raw[2 * (tid + 768) + 1];
        if (v) atomicOr(&s_any, 1u);
        __syncthreads();
        if (tid == 0) g_idx_is64 = (s_any == 0u) ? 1 : 0;
    }

    // ---- zero this block's 64-element slice of centrality ----
    if (cent != nullptr && tid < 64)
        cent[(size_t)blk * 64 + tid] = 0.0f;

    const size_t src_off = ((size_t)b * C + (size_t)g * D) * N + n0;
    float* dst = g_qkv + ((size_t)bg * N + n0) * 32;

    {   // queryandkey -> row offset [0:16)
        const float* src = qk + src_off;
        #pragma unroll
        for (int r = 0; r < 4; r++) {
            int e = tid + r * 256;
            int j = e >> 6, nn = e & 63;
            tile[j][nn] = src[(size_t)j * N + nn];
        }
        __syncthreads();
        #pragma unroll
        for (int r = 0; r < 4; r++) {
            int e = tid + r * 256;
            int nn = e >> 4, j = e & 15;
            dst[nn * 32 + j] = tile[j][nn];
        }
        __syncthreads();
    }
    {   // value -> row offset [16:32)
        const float* src = val + src_off;
        #pragma unroll
        for (int r = 0; r < 4; r++) {
            int e = tid + r * 256;
            int j = e >> 6, nn = e & 63;
            tile[j][nn] = src[(size_t)j * N + nn];
        }
        __syncthreads();
        #pragma unroll
        for (int r = 0; r < 4; r++) {
            int e = tid + r * 256;
            int nn = e >> 4, j = e & 15;
            dst[nn * 32 + 16 + j] = tile[j][nn];
        }
    }
}

// ---------------------------------------------------------------------------
// Fused attention, 512 points per block (16 iterations, 8-lane core).
// 8 lanes per point: lanes 0-3 key channels, lanes 4-7 value channels; one
// neighbor 128B row = ONE LDG.128 per warp-quad-group (1 L1 wavefront/line —
// half the 4-lane core's 2). Centrality accumulates in block-local smem
// (SM-side atomics), flushed once as coalesced global adds (R15 win).
// Dot: butterfly xor1+xor2+xor4 over zeroed value-lane partials.
// Softmax shifted by the first logit (shift-invariant, no max pre-pass).
// ---------------------------------------------------------------------------
__global__ void __launch_bounds__(256, 4) attn_kernel(
    const void* __restrict__ idx_raw,
    float* __restrict__ out,           // feature region
    float* __restrict__ cent)          // centrality region (may be null)
{
    __shared__ float s_cent[N];         // 16KB per-block centrality accumulator
    __shared__ int   s_off[PTS][17];    // [point][k]: neighbor byte offsets
    __shared__ float ftile[PTS][D + 1];

    const int blk   = blockIdx.x;
    const int chunk = blk % CHUNKS;
    const int bg    = blk / CHUNKS;
    const int g     = bg % G;
    const int b     = bg / G;

    const int tid = threadIdx.x;
    const int p   = tid >> 3;           // point within iteration (0..31)
    const int L   = tid & 7;            // lane within point (0..7)
    const unsigned FULL = 0xffffffffu;

    const float keysel = (L < 4) ? 1.0f : 0.0f;   // value lanes contribute 0
    const size_t bgN = (size_t)bg * N;
    const bool do_cent = (cent != nullptr);

    // ---- zero the smem centrality accumulator ----
    float4* sc4 = reinterpret_cast<float4*>(s_cent);
    #pragma unroll
    for (int r = 0; r < 4; r++)
        sc4[tid + r * 256] = make_float4(0.f, 0.f, 0.f, 0.f);
    __syncthreads();

    // Gather base pointer: folds bg-slab and this lane's 16B sub-offset.
    const char* gbase = reinterpret_cast<const char*>(g_qkv)
                      + bgN * 128 + (size_t)L * 16;
    const int is64 = g_idx_is64;

    for (int it = 0; it < ITERS; it++) {
        const int n0 = chunk * CHUNK_PTS + it * PTS;
        const int n  = n0 + p;

        // --- lane L loads neighbors 2L, 2L+1 (dtype-dispatched), clamp ---
        const size_t ibase = ((size_t)b * N + n) * K + 2 * L;
        int i0, i1;
        if (is64) {
            longlong2 e = *reinterpret_cast<const longlong2*>(
                reinterpret_cast<const long long*>(idx_raw) + ibase);
            i0 = (int)e.x; i1 = (int)e.y;
        } else {
            int2 e = *reinterpret_cast<const int2*>(
                reinterpret_cast<const int*>(idx_raw) + ibase);
            i0 = e.x; i1 = e.y;
        }
        i0 = min(max(i0, 0), N - 1);
        i1 = min(max(i1, 0), N - 1);
        s_off[p][2 * L]     = i0 << 7;      // 128 bytes per point row
        s_off[p][2 * L + 1] = i1 << 7;
        __syncwarp();

        // --- query (key-part of own row; lanes 4-7 duplicate lanes 0-3) ---
        const float4 q = *reinterpret_cast<const float4*>(
            reinterpret_cast<const char*>(g_qkv)
            + (bgN + n) * 128 + (size_t)(L & 3) * 16);

        // --- single pass, depth-3 pipelined gathers ---
        float s0 = 0.0f;                    // shift = first logit
        float sum = 0.0f;
        float my_e0 = 0.0f, my_e1 = 0.0f;   // exps of this lane's 2 neighbors
        float4 acc = make_float4(0.f, 0.f, 0.f, 0.f);

        float4 kv_a = *reinterpret_cast<const float4*>(gbase + s_off[p][0]);
        float4 kv_b = *reinterpret_cast<const float4*>(gbase + s_off[p][1]);

        #pragma unroll
        for (int k = 0; k < 16; k++) {
            float4 kv = kv_a;
            kv_a = kv_b;
            if (k + 2 < 16)
                kv_b = *reinterpret_cast<const float4*>(gbase + s_off[p][k + 2]);

            // partial dot (key lanes only); butterfly across all 8 lanes
            float s = fmaf(q.x, kv.x, fmaf(q.y, kv.y, fmaf(q.z, kv.z, q.w * kv.w)));
            s *= keysel;
            s += __shfl_xor_sync(FULL, s, 1);
            s += __shfl_xor_sync(FULL, s, 2);
            s += __shfl_xor_sync(FULL, s, 4);         // all 8 lanes: full dot
            if (k == 0) s0 = s;
            float e = __expf(s - s0);       // e = 1 for k == 0
            if (2 * L == k)     my_e0 = e;  // compile-time k: ISETP + SEL
            if (2 * L + 1 == k) my_e1 = e;
            sum += e;
            acc.x = fmaf(e, kv.x, acc.x);   // value channels live in lanes 4-7
            acc.y = fmaf(e, kv.y, acc.y);
            acc.z = fmaf(e, kv.z, acc.z);
            acc.w = fmaf(e, kv.w, acc.w);
        }
        const float inv = 1.0f / sum;

        // --- centrality: accumulate into block-local smem (SM-side) ---
        if (do_cent) {
            atomicAdd(&s_cent[i0], my_e0 * inv);
            atomicAdd(&s_cent[i1], my_e1 * inv);
        }

        // --- feature: lanes 4-7 hold the value accumulation ---
        if (L >= 4) {
            int c0 = (L - 4) * 4;
            ftile[p][c0 + 0] = acc.x * inv;
            ftile[p][c0 + 1] = acc.y * inv;
            ftile[p][c0 + 2] = acc.z * inv;
            ftile[p][c0 + 3] = acc.w * inv;
        }
        __syncthreads();

        // --- coalesced write in (B, C, N) layout: 16 rows x 32 points ---
        float* fout = out + ((size_t)b * C + (size_t)g * D) * N + n0;
        #pragma unroll
        for (int r = 0; r < 2; r++) {
            int e = tid + r * 256;
            int j = e >> 5, nn = e & 31;
            fout[(size_t)j * N + nn] = ftile[nn][j];
        }
        __syncthreads();   // ftile reused next iteration
    }

    // ---- flush: 4096 coalesced global adds (8 slabs share each cent row) ----
    if (do_cent) {
        float* cbase = cent + bgN;
        #pragma unroll
        for (int r = 0; r < 16; r++) {
            int i = tid + r * 256;
            atomicAdd(&cbase[i], s_cent[i]);
        }
    }
}

// ---------------------------------------------------------------------------
// Launch
// ---------------------------------------------------------------------------
extern "C" void kernel_launch(void* const* d_in, const int* in_sizes, int n_in,
                              void* d_out, int out_size)
{
    // Resolve inputs by element count (robust to ordering)
    const float* qk  = nullptr;
    const float* val = nullptr;
    const void*  idx = nullptr;

    for (int i = 0; i < n_in; i++) {
        if (in_sizes[i] == FEAT_ELEMS) {
            if (qk == nullptr)       qk  = (const float*)d_in[i];
            else if (val == nullptr) val = (const float*)d_in[i];
        } else if (in_sizes[i] == IDX_ELEMS) {
            idx = d_in[i];
        }
    }
    if (qk == nullptr || val == nullptr || idx == nullptr) {
        qk  = (const float*)d_in[4];
        val = (const float*)d_in[5];
        idx = d_in[6];
    }

    float* out  = (float*)d_out;                   // feature (B*C*N) first
    float* cent = nullptr;                         // then centrality (B*G*N)
    if (out_size >= FEAT_ELEMS + CENT_ELEMS)
        cent = out + (size_t)FEAT_ELEMS;

    transpose_kernel<<<TBLOCKS, 256>>>(qk, val, (const unsigned int*)idx, cent);
    attn_kernel<<<ABLOCKS, 256>>>(idx, out, cent);
}

// round 17
// speedup vs baseline: 1.1105x; 1.1105x over previous
#include <cuda_runtime.h>
#include <cstddef>

// Problem constants (fixed by setup_inputs)
constexpr int B = 8;
constexpr int C = 144;
constexpr int N = 4096;
constexpr int K = 16;
constexpr int G = 9;
constexpr int D = 16;          // C / G
constexpr int NTILE = 64;      // points per transpose block
constexpr int NBLK_N = N / NTILE;

constexpr int FEAT_ELEMS = B * C * N;      // 4718592
constexpr int CENT_ELEMS = B * G * N;      // 294912
constexpr int IDX_ELEMS  = B * N * K;      // 524288
constexpr int TBLOCKS    = B * G * NBLK_N; // 4608 (= CENT_ELEMS / 64)

constexpr int PTS      = 64;               // points per attn inner iteration
constexpr int CHUNKS   = 8;                // blocks per bg slab
constexpr int CHUNK_PTS = N / CHUNKS;      // 512 points per block
constexpr int ITERS    = CHUNK_PTS / PTS;  // 8 inner iterations
constexpr int ABLOCKS  = B * G * CHUNKS;   // 576

// Fused scratch: per point one 128B row = [key(16 floats) | value(16 floats)].
__device__ __align__(128) float g_qkv[(size_t)B * G * N * 32];

// Index-dtype flag: 1 if idx_knn is int64, 0 if int32.
__device__ int g_idx_is64;

// 256-bit global load: 8 consecutive f32 (32B-aligned address).
struct F8 { float x0, x1, x2, x3, x4, x5, x6, x7; };
__device__ __forceinline__ F8 ldg256(const char* p)
{
    F8 v;
    asm("ld.global.v8.b32 {%0,%1,%2,%3,%4,%5,%6,%7}, [%8];"
        : "=f"(v.x0), "=f"(v.x1), "=f"(v.x2), "=f"(v.x3),
          "=f"(v.x4), "=f"(v.x5), "=f"(v.x6), "=f"(v.x7)
        : "l"(p));
    return v;
}

// ---------------------------------------------------------------------------
// Transpose (B, C, N) -> fused (B*G, N, 32) rows, zero the centrality region,
// and (block 0 only) detect the idx dtype.
// ---------------------------------------------------------------------------
__global__ void __launch_bounds__(256) transpose_kernel(
    const float* __restrict__ qk, const float* __restrict__ val,
    const unsigned int* __restrict__ idx_raw,
    float* __restrict__ cent)
{
    __shared__ float tile[D][NTILE + 1];
    __shared__ unsigned int s_any;

    const int blk   = blockIdx.x;
    const int ntile = blk % NBLK_N;
    const int bg    = blk / NBLK_N;
    const int g     = bg % G;
    const int b     = bg / G;
    const int n0    = ntile * NTILE;
    const int tid   = threadIdx.x;

    // ---- block 0: idx dtype detection (odd words all zero => int64) ----
    if (blk == 0) {
        if (tid == 0) s_any = 0u;
        __syncthreads();
        unsigned int v = idx_raw[2 * tid + 1] |
                         idx_raw[2 * (tid + 256) + 1] |
                         idx_raw[2 * (tid + 512) + 1] |
                         idx_raw[2 * (tid + 768) + 1];
        if (v) atomicOr(&s_any, 1u);
        __syncthreads();
        if (tid == 0) g_idx_is64 = (s_any == 0u) ? 1 : 0;
    }

    // ---- zero this block's 64-element slice of centrality ----
    if (cent != nullptr && tid < 64)
        cent[(size_t)blk * 64 + tid] = 0.0f;

    const size_t src_off = ((size_t)b * C + (size_t)g * D) * N + n0;
    float* dst = g_qkv + ((size_t)bg * N + n0) * 32;

    {   // queryandkey -> row offset [0:16)
        const float* src = qk + src_off;
        #pragma unroll
        for (int r = 0; r < 4; r++) {
            int e = tid + r * 256;
            int j = e >> 6, nn = e & 63;
            tile[j][nn] = src[(size_t)j * N + nn];
        }
        __syncthreads();
        #pragma unroll
        for (int r = 0; r < 4; r++) {
            int e = tid + r * 256;
            int nn = e >> 4, j = e & 15;
            dst[nn * 32 + j] = tile[j][nn];
        }
        __syncthreads();
    }
    {   // value -> row offset [16:32)
        const float* src = val + src_off;
        #pragma unroll
        for (int r = 0; r < 4; r++) {
            int e = tid + r * 256;
            int j = e >> 6, nn = e & 63;
            tile[j][nn] = src[(size_t)j * N + nn];
        }
        __syncthreads();
        #pragma unroll
        for (int r = 0; r < 4; r++) {
            int e = tid + r * 256;
            int nn = e >> 4, j = e & 15;
            dst[nn * 32 + 16 + j] = tile[j][nn];
        }
    }
}

// ---------------------------------------------------------------------------
// Fused attention, 512 points per block (8 iterations of the 4-lane core).
//   lane 0: key[0:8]  lane 1: key[8:16]  lane 2: val[0:8]  lane 3: val[8:16]
// Each lane fetches its 32B slice of the neighbor's 128B row with ONE
// 256-bit load (Blackwell ld.global.v8) — halving LSU issue and L1
// wavefronts vs the 2x float4 version (R15) at identical per-point economy.
// Centrality accumulates in block-local smem, flushed once coalesced (R15).
// Dot: butterfly xor1+xor2 over zeroed value-lane partials.
// Softmax shifted by the first logit (shift-invariant, no max pre-pass).
// ---------------------------------------------------------------------------
__global__ void __launch_bounds__(256, 4) attn_kernel(
    const void* __restrict__ idx_raw,
    float* __restrict__ out,           // feature region
    float* __restrict__ cent)          // centrality region (may be null)
{
    __shared__ float s_cent[N];         // 16KB per-block centrality accumulator
    __shared__ int   s_off[PTS][17];    // [point][k]: neighbor byte offsets
    __shared__ float ftile[PTS][D + 1];

    const int blk   = blockIdx.x;
    const int chunk = blk % CHUNKS;
    const int bg    = blk / CHUNKS;
    const int g     = bg % G;
    const int b     = bg / G;

    const int tid = threadIdx.x;
    const int p   = tid >> 2;           // point within iteration (0..63)
    const int L   = tid & 3;            // lane within point (0..3)
    const unsigned FULL = 0xffffffffu;

    const float keysel = (L < 2) ? 1.0f : 0.0f;   // value lanes contribute 0
    const size_t bgN = (size_t)bg * N;
    const bool do_cent = (cent != nullptr);

    // ---- zero the smem centrality accumulator ----
    float4* sc4 = reinterpret_cast<float4*>(s_cent);
    #pragma unroll
    for (int r = 0; r < 4; r++)
        sc4[tid + r * 256] = make_float4(0.f, 0.f, 0.f, 0.f);
    __syncthreads();

    // Gather base pointer: folds bg-slab and this lane's 32B sub-offset.
    const char* gbase = reinterpret_cast<const char*>(g_qkv)
                      + bgN * 128 + (size_t)L * 32;
    const int is64 = g_idx_is64;

    for (int it = 0; it < ITERS; it++) {
        const int n0 = chunk * CHUNK_PTS + it * PTS;
        const int n  = n0 + p;

        // --- lane L loads neighbors 4L..4L+3 (dtype-dispatched), clamp ---
        const size_t ibase = ((size_t)b * N + n) * K + 4 * L;
        int mi[4];
        if (is64) {
            const long long* ip = reinterpret_cast<const long long*>(idx_raw) + ibase;
            longlong2 e0 = *reinterpret_cast<const longlong2*>(ip);
            longlong2 e1 = *reinterpret_cast<const longlong2*>(ip + 2);
            mi[0] = (int)e0.x; mi[1] = (int)e0.y; mi[2] = (int)e1.x; mi[3] = (int)e1.y;
        } else {
            int4 e = *reinterpret_cast<const int4*>(
                reinterpret_cast<const int*>(idx_raw) + ibase);
            mi[0] = e.x; mi[1] = e.y; mi[2] = e.z; mi[3] = e.w;
        }
        #pragma unroll
        for (int i = 0; i < 4; i++) {
            mi[i] = min(max(mi[i], 0), N - 1);
            s_off[p][4 * L + i] = mi[i] << 7;   // 128 bytes per point row
        }
        __syncwarp();

        // --- query half (one 256-bit load; value lanes mirror key halves) ---
        const F8 q = ldg256(reinterpret_cast<const char*>(g_qkv)
                            + (bgN + n) * 128 + (size_t)(L & 1) * 32);

        // --- single pass, depth-2 pipelined 256-bit gathers ---
        float s0 = 0.0f;                    // shift = first logit
        float sum = 0.0f;
        float my_e[4] = {0.f, 0.f, 0.f, 0.f};
        float acc[8] = {0.f, 0.f, 0.f, 0.f, 0.f, 0.f, 0.f, 0.f};

        F8 kva = ldg256(gbase + s_off[p][0]);

        #pragma unroll
        for (int k = 0; k < 16; k++) {
            F8 kv = kva;
            if (k + 1 < 16)
                kva = ldg256(gbase + s_off[p][k + 1]);

            // 8-channel partial dot (key lanes); butterfly over the quad
            float s = fmaf(q.x0, kv.x0, fmaf(q.x1, kv.x1,
                      fmaf(q.x2, kv.x2, fmaf(q.x3, kv.x3,
                      fmaf(q.x4, kv.x4, fmaf(q.x5, kv.x5,
                      fmaf(q.x6, kv.x6, q.x7 * kv.x7)))))));
            s *= keysel;
            s += __shfl_xor_sync(FULL, s, 1);
            s += __shfl_xor_sync(FULL, s, 2);   // all 4 lanes: full dot
            if (k == 0) s0 = s;
            float e = __expf(s - s0);           // e = 1 for k == 0
            if ((k >> 2) == L) my_e[k & 3] = e; // compile-time k: ISETP + SEL
            sum += e;
            acc[0] = fmaf(e, kv.x0, acc[0]);    // value lanes accumulate
            acc[1] = fmaf(e, kv.x1, acc[1]);
            acc[2] = fmaf(e, kv.x2, acc[2]);
            acc[3] = fmaf(e, kv.x3, acc[3]);
            acc[4] = fmaf(e, kv.x4, acc[4]);
            acc[5] = fmaf(e, kv.x5, acc[5]);
            acc[6] = fmaf(e, kv.x6, acc[6]);
            acc[7] = fmaf(e, kv.x7, acc[7]);
        }
        const float inv = 1.0f / sum;

        // --- centrality: accumulate into block-local smem (SM-side) ---
        if (do_cent) {
            #pragma unroll
            for (int i = 0; i < 4; i++)
                atomicAdd(&s_cent[mi[i]], my_e[i] * inv);
        }

        // --- feature: lanes 2-3 hold value halves ---
        if (L >= 2) {
            int c0 = (L - 2) * 8;
            #pragma unroll
            for (int i = 0; i < 8; i++)
                ftile[p][c0 + i] = acc[i] * inv;
        }
        __syncthreads();

        // --- coalesced write in (B, C, N) layout: 16 rows x 64 points ---
        float* fout = out + ((size_t)b * C + (size_t)g * D) * N + n0;
        #pragma unroll
        for (int r = 0; r < 4; r++) {
            int e = tid + r * 256;
            int j = e >> 6, nn = e & 63;
            fout[(size_t)j * N + nn] = ftile[nn][j];
        }
        __syncthreads();   // ftile reused next iteration
    }

    // ---- flush: 4096 coalesced global adds (8 slabs share each cent row) ----
    if (do_cent) {
        float* cbase = cent + bgN;
        #pragma unroll
        for (int r = 0; r < 16; r++) {
            int i = tid + r * 256;
            atomicAdd(&cbase[i], s_cent[i]);
        }
    }
}

// ---------------------------------------------------------------------------
// Launch
// ---------------------------------------------------------------------------
extern "C" void kernel_launch(void* const* d_in, const int* in_sizes, int n_in,
                              void* d_out, int out_size)
{
    // Resolve inputs by element count (robust to ordering)
    const float* qk  = nullptr;
    const float* val = nullptr;
    const void*  idx = nullptr;

    for (int i = 0; i < n_in; i++) {
        if (in_sizes[i] == FEAT_ELEMS) {
            if (qk == nullptr)       qk  = (const float*)d_in[i];
            else if (val == nullptr) val = (const float*)d_in[i];
        } else if (in_sizes[i] == IDX_ELEMS) {
            idx = d_in[i];
        }
    }
    if (qk == nullptr || val == nullptr || idx == nullptr) {
        qk  = (const float*)d_in[4];
        val = (const float*)d_in[5];
        idx = d_in[6];
    }

    float* out  = (float*)d_out;                   // feature (B*C*N) first
    float* cent = nullptr;                         // then centrality (B*G*N)
    if (out_size >= FEAT_ELEMS + CENT_ELEMS)
        cent = out + (size_t)FEAT_ELEMS;

    transpose_kernel<<<TBLOCKS, 256>>>(qk, val, (const unsigned int*)idx, cent);
    attn_kernel<<<ABLOCKS, 256>>>(idx, out, cent);
}